// round 3
// baseline (speedup 1.0000x reference)
#include <cuda_runtime.h>

#define NEU   64
#define HID   32
#define GD    103
#define N_MAX 2000128
#define B_MAX 8192

// Scratch (no allocations allowed in kernel_launch)
__device__ float        g_logit[N_MAX];
__device__ float        g_e[N_MAX];
__device__ float        g_G[B_MAX * HID];
__device__ unsigned int g_maxenc[B_MAX];
__device__ float        g_sum[B_MAX];

// Monotonic float <-> uint encoding for atomicMax on floats
__device__ __forceinline__ unsigned int enc_f(float f) {
    unsigned int u = __float_as_uint(f);
    return (u & 0x80000000u) ? ~u : (u | 0x80000000u);
}
__device__ __forceinline__ float dec_f(unsigned int u) {
    u = (u & 0x80000000u) ? (u & 0x7FFFFFFFu) : ~u;
    return __uint_as_float(u);
}

// ---------------------------------------------------------------------------
// k_init: reset per-segment accumulators (must run every replay)
// ---------------------------------------------------------------------------
__global__ void k_init(int b) {
    int i = blockIdx.x * blockDim.x + threadIdx.x;
    if (i < b) {
        g_maxenc[i] = 0u;      // encodes <= -inf
        g_sum[i]    = 0.0f;
    }
}

// ---------------------------------------------------------------------------
// k_graph: G[b][h] = b1[h] + sum_d global_fea[b][d] * W1[(64+d)][h]
// one warp per graph
// ---------------------------------------------------------------------------
__global__ void k_graph(const float* __restrict__ gf,
                        const float* __restrict__ W1,
                        const float* __restrict__ b1, int b) {
    int warp = (blockIdx.x * blockDim.x + threadIdx.x) >> 5;
    int lane = threadIdx.x & 31;
    if (warp >= b) return;

    const float* row = gf + (size_t)warp * GD;
    float r0 = row[lane];
    float r1 = row[32 + lane];
    float r2 = row[64 + lane];
    float r3 = (lane < (GD - 96)) ? row[96 + lane] : 0.0f;

    float acc = b1[lane];
#pragma unroll
    for (int d = 0; d < GD; d++) {
        float v;
        if      (d < 32) v = __shfl_sync(0xFFFFFFFFu, r0, d);
        else if (d < 64) v = __shfl_sync(0xFFFFFFFFu, r1, d - 32);
        else if (d < 96) v = __shfl_sync(0xFFFFFFFFu, r2, d - 64);
        else             v = __shfl_sync(0xFFFFFFFFu, r3, d - 96);
        acc = fmaf(v, W1[(NEU + d) * HID + lane], acc);
    }
    g_G[warp * HID + lane] = acc;
}

// ---------------------------------------------------------------------------
// k_logits: per node  logit = b2 + sum_h softplus(x.W1a + G[seg])[h] * W2[h]
// thread-per-node, W1a in SMEM; warp-segmented atomicMax for per-graph max
// ---------------------------------------------------------------------------
__global__ void __launch_bounds__(256)
k_logits(const float* __restrict__ x,
         const int* __restrict__ nb,
         const float* __restrict__ W1,
         const float* __restrict__ W2,
         const float* __restrict__ b2, int n) {
    __shared__ float sW1[NEU * HID];   // first 64 rows of W1
    __shared__ float sW2[HID];
    __shared__ float sb2;

    for (int t = threadIdx.x; t < NEU * HID; t += blockDim.x) sW1[t] = W1[t];
    if (threadIdx.x < HID) sW2[threadIdx.x] = W2[threadIdx.x];
    if (threadIdx.x == 0)  sb2 = b2[0];
    __syncthreads();

    int i = blockIdx.x * blockDim.x + threadIdx.x;
    int lane = threadIdx.x & 31;
    bool valid = (i < n);

    int   seg   = -1;
    float logit = -3.4e38f;

    if (valid) {
        seg = nb[i];

        float acc[HID];
        const float4* Gp = (const float4*)(g_G + seg * HID);
#pragma unroll
        for (int q = 0; q < 8; q++) {
            float4 v = Gp[q];
            acc[4*q+0] = v.x; acc[4*q+1] = v.y; acc[4*q+2] = v.z; acc[4*q+3] = v.w;
        }

        const float4* xp = (const float4*)(x + (size_t)i * NEU);
#pragma unroll
        for (int half = 0; half < 2; half++) {
            float xv[32];
#pragma unroll
            for (int q = 0; q < 8; q++) {
                float4 v = xp[half * 8 + q];
                xv[4*q+0] = v.x; xv[4*q+1] = v.y; xv[4*q+2] = v.z; xv[4*q+3] = v.w;
            }
#pragma unroll
            for (int k = 0; k < 32; k++) {
                float xk = xv[k];
                const float4* w = (const float4*)(sW1 + (half * 32 + k) * HID);
#pragma unroll
                for (int q = 0; q < 8; q++) {
                    float4 wv = w[q];
                    acc[4*q+0] = fmaf(xk, wv.x, acc[4*q+0]);
                    acc[4*q+1] = fmaf(xk, wv.y, acc[4*q+1]);
                    acc[4*q+2] = fmaf(xk, wv.z, acc[4*q+2]);
                    acc[4*q+3] = fmaf(xk, wv.w, acc[4*q+3]);
                }
            }
        }

        float lg = sb2;
#pragma unroll
        for (int h = 0; h < HID; h++) {
            float a  = acc[h];
            float sp = (a > 20.0f) ? a : __logf(1.0f + __expf(a));
            lg = fmaf(sp, sW2[h], lg);
        }
        logit = lg;
        g_logit[i] = lg;
    }

    // warp segmented suffix-max (node_batch sorted -> runs are contiguous)
    float v = logit;
#pragma unroll
    for (int off = 1; off < 32; off <<= 1) {
        int   oseg = __shfl_down_sync(0xFFFFFFFFu, seg, off);
        float ov   = __shfl_down_sync(0xFFFFFFFFu, v,   off);
        if (lane + off < 32 && oseg == seg) v = fmaxf(v, ov);
    }
    int  pseg = __shfl_up_sync(0xFFFFFFFFu, seg, 1);
    bool head = (lane == 0) || (pseg != seg);
    if (head && seg >= 0) atomicMax(&g_maxenc[seg], enc_f(v));
}

// ---------------------------------------------------------------------------
// k_exp: e = exp(logit - max[seg]); segmented atomicAdd of sums
// ---------------------------------------------------------------------------
__global__ void __launch_bounds__(256)
k_exp(const int* __restrict__ nb, int n) {
    int i = blockIdx.x * blockDim.x + threadIdx.x;
    int lane = threadIdx.x & 31;

    int   seg = -1;
    float e   = 0.0f;
    if (i < n) {
        seg = nb[i];
        float mx = dec_f(g_maxenc[seg]);
        e = __expf(g_logit[i] - mx);
        g_e[i] = e;
    }

    // warp segmented suffix-sum
#pragma unroll
    for (int off = 1; off < 32; off <<= 1) {
        int   oseg = __shfl_down_sync(0xFFFFFFFFu, seg, off);
        float oe   = __shfl_down_sync(0xFFFFFFFFu, e,   off);
        if (lane + off < 32 && oseg == seg) e += oe;
    }
    int  pseg = __shfl_up_sync(0xFFFFFFFFu, seg, 1);
    bool head = (lane == 0) || (pseg != seg);
    if (head && seg >= 0) atomicAdd(&g_sum[seg], e);
}

// ---------------------------------------------------------------------------
// k_div: out = e / sum[seg]
// ---------------------------------------------------------------------------
__global__ void __launch_bounds__(256)
k_div(const int* __restrict__ nb, float* __restrict__ out, int n) {
    int i = blockIdx.x * blockDim.x + threadIdx.x;
    if (i < n) {
        int seg = nb[i];
        out[i] = g_e[i] / g_sum[seg];
    }
}

// ---------------------------------------------------------------------------
extern "C" void kernel_launch(void* const* d_in, const int* in_sizes, int n_in,
                              void* d_out, int out_size) {
    const float* x   = (const float*)d_in[0];
    const int*   nb  = (const int*)d_in[1];
    const float* gf  = (const float*)d_in[2];
    const float* W1  = (const float*)d_in[3];
    const float* b1  = (const float*)d_in[4];
    const float* W2  = (const float*)d_in[5];
    const float* b2  = (const float*)d_in[6];
    float*       out = (float*)d_out;

    int n = in_sizes[0] / NEU;   // nodes
    int b = in_sizes[2] / GD;    // graphs

    k_init<<<(b + 255) / 256, 256>>>(b);
    k_graph<<<(b + 7) / 8, 256>>>(gf, W1, b1, b);

    int blocks = (n + 255) / 256;
    k_logits<<<blocks, 256>>>(x, nb, W1, W2, b2, n);
    k_exp<<<blocks, 256>>>(nb, n);
    k_div<<<blocks, 256>>>(nb, out, n);
}

// round 4
// speedup vs baseline: 1.0002x; 1.0002x over previous
#include <cuda_runtime.h>

#define NEU   64
#define HID   32
#define GD    103
#define N_MAX 2000128
#define B_MAX 8192

typedef unsigned long long ull;

// Scratch (no allocations allowed in kernel_launch)
__device__ float        g_logit[N_MAX];
__device__ float        g_G[B_MAX * HID];
__device__ unsigned int g_maxenc[B_MAX];
__device__ float        g_sum[B_MAX];

// Monotonic float <-> uint encoding for atomicMax on floats
__device__ __forceinline__ unsigned int enc_f(float f) {
    unsigned int u = __float_as_uint(f);
    return (u & 0x80000000u) ? ~u : (u | 0x80000000u);
}
__device__ __forceinline__ float dec_f(unsigned int u) {
    u = (u & 0x80000000u) ? (u & 0x7FFFFFFFu) : ~u;
    return __uint_as_float(u);
}

// Packed f32x2 helpers (FFMA2 — only reachable via PTX)
__device__ __forceinline__ ull fma2(ull a, ull b, ull c) {
    ull d;
    asm("fma.rn.f32x2 %0, %1, %2, %3;" : "=l"(d) : "l"(a), "l"(b), "l"(c));
    return d;
}
__device__ __forceinline__ ull pack2(float lo, float hi) {
    ull d;
    asm("mov.b64 %0, {%1, %2};" : "=l"(d) : "f"(lo), "f"(hi));
    return d;
}
__device__ __forceinline__ void unpack2(ull v, float& lo, float& hi) {
    asm("mov.b64 {%0, %1}, %2;" : "=f"(lo), "=f"(hi) : "l"(v));
}

// ---------------------------------------------------------------------------
// k_init: reset per-segment accumulators (must run every replay)
// ---------------------------------------------------------------------------
__global__ void k_init(int b) {
    int i = blockIdx.x * blockDim.x + threadIdx.x;
    if (i < b) {
        g_maxenc[i] = 0u;      // encodes <= -inf
        g_sum[i]    = 0.0f;
    }
}

// ---------------------------------------------------------------------------
// k_graph: G[b][h] = b1[h] + sum_d global_fea[b][d] * W1[(64+d)][h]
// one warp per graph
// ---------------------------------------------------------------------------
__global__ void k_graph(const float* __restrict__ gf,
                        const float* __restrict__ W1,
                        const float* __restrict__ b1, int b) {
    int warp = (blockIdx.x * blockDim.x + threadIdx.x) >> 5;
    int lane = threadIdx.x & 31;
    if (warp >= b) return;

    const float* row = gf + (size_t)warp * GD;
    float r0 = row[lane];
    float r1 = row[32 + lane];
    float r2 = row[64 + lane];
    float r3 = (lane < (GD - 96)) ? row[96 + lane] : 0.0f;

    float acc = b1[lane];
#pragma unroll
    for (int d = 0; d < GD; d++) {
        float v;
        if      (d < 32) v = __shfl_sync(0xFFFFFFFFu, r0, d);
        else if (d < 64) v = __shfl_sync(0xFFFFFFFFu, r1, d - 32);
        else if (d < 96) v = __shfl_sync(0xFFFFFFFFu, r2, d - 64);
        else             v = __shfl_sync(0xFFFFFFFFu, r3, d - 96);
        acc = fmaf(v, W1[(NEU + d) * HID + lane], acc);
    }
    g_G[warp * HID + lane] = acc;
}

// ---------------------------------------------------------------------------
// k_logits: per node  logit = b2 + sum_h softplus(x.W1a + G[seg])[h] * W2[h]
// packed-K f32x2 GEMV: acc2[h] = (sum over even k, sum over odd k)
// ---------------------------------------------------------------------------
__global__ void __launch_bounds__(256)
k_logits(const float* __restrict__ x,
         const int* __restrict__ nb,
         const float* __restrict__ W1,
         const float* __restrict__ W2,
         const float* __restrict__ b2, int n) {
    // sW1p[k2*32 + h] = ( W1[2*k2][h], W1[2*k2+1][h] )
    __shared__ ull   sW1p[(NEU / 2) * HID];
    __shared__ float sW2[HID];
    __shared__ float sb2;

    for (int t = threadIdx.x; t < (NEU / 2) * HID; t += blockDim.x) {
        int k2 = t >> 5, h = t & 31;
        sW1p[t] = pack2(W1[(2 * k2) * HID + h], W1[(2 * k2 + 1) * HID + h]);
    }
    if (threadIdx.x < HID) sW2[threadIdx.x] = W2[threadIdx.x];
    if (threadIdx.x == 0)  sb2 = b2[0];
    __syncthreads();

    int i = blockIdx.x * blockDim.x + threadIdx.x;
    int lane = threadIdx.x & 31;
    bool valid = (i < n);

    int   seg   = -1;
    float logit = -3.4e38f;

    if (valid) {
        seg = nb[i];

        ull acc2[HID];
        const float4* Gp = (const float4*)(g_G + seg * HID);
#pragma unroll
        for (int q = 0; q < 8; q++) {
            float4 v = Gp[q];
            acc2[4*q+0] = pack2(v.x, 0.0f);
            acc2[4*q+1] = pack2(v.y, 0.0f);
            acc2[4*q+2] = pack2(v.z, 0.0f);
            acc2[4*q+3] = pack2(v.w, 0.0f);
        }

        // x row: 64 floats = 16 x ulonglong2; each ull = (x_{2k}, x_{2k+1})
        const ulonglong2* xp = (const ulonglong2*)(x + (size_t)i * NEU);
#pragma unroll
        for (int q = 0; q < 16; q++) {
            ulonglong2 xq = xp[q];               // k2 = 2q and 2q+1
            const ull* w0 = &sW1p[(2 * q) * HID];
            const ull* w1 = &sW1p[(2 * q + 1) * HID];
#pragma unroll
            for (int h = 0; h < HID; h++)
                acc2[h] = fma2(xq.x, w0[h], acc2[h]);
#pragma unroll
            for (int h = 0; h < HID; h++)
                acc2[h] = fma2(xq.y, w1[h], acc2[h]);
        }

        float lg = sb2;
#pragma unroll
        for (int h = 0; h < HID; h++) {
            float lo, hi;
            unpack2(acc2[h], lo, hi);
            float a  = lo + hi;
            float sp = (a > 20.0f) ? a : __logf(1.0f + __expf(a));
            lg = fmaf(sp, sW2[h], lg);
        }
        logit = lg;
        g_logit[i] = lg;
    }

    // warp segmented suffix-max (node_batch sorted -> runs are contiguous)
    float v = logit;
#pragma unroll
    for (int off = 1; off < 32; off <<= 1) {
        int   oseg = __shfl_down_sync(0xFFFFFFFFu, seg, off);
        float ov   = __shfl_down_sync(0xFFFFFFFFu, v,   off);
        if (lane + off < 32 && oseg == seg) v = fmaxf(v, ov);
    }
    int  pseg = __shfl_up_sync(0xFFFFFFFFu, seg, 1);
    bool head = (lane == 0) || (pseg != seg);
    if (head && seg >= 0) atomicMax(&g_maxenc[seg], enc_f(v));
}

// ---------------------------------------------------------------------------
// k_exp: e = exp(logit - max[seg]); segmented atomicAdd of sums (e not stored)
// ---------------------------------------------------------------------------
__global__ void __launch_bounds__(256)
k_exp(const int* __restrict__ nb, int n) {
    int i = blockIdx.x * blockDim.x + threadIdx.x;
    int lane = threadIdx.x & 31;

    int   seg = -1;
    float e   = 0.0f;
    if (i < n) {
        seg = nb[i];
        float mx = dec_f(g_maxenc[seg]);
        e = __expf(g_logit[i] - mx);
    }

    // warp segmented suffix-sum
#pragma unroll
    for (int off = 1; off < 32; off <<= 1) {
        int   oseg = __shfl_down_sync(0xFFFFFFFFu, seg, off);
        float oe   = __shfl_down_sync(0xFFFFFFFFu, e,   off);
        if (lane + off < 32 && oseg == seg) e += oe;
    }
    int  pseg = __shfl_up_sync(0xFFFFFFFFu, seg, 1);
    bool head = (lane == 0) || (pseg != seg);
    if (head && seg >= 0) atomicAdd(&g_sum[seg], e);
}

// ---------------------------------------------------------------------------
// k_div: out = exp(logit - max[seg]) / sum[seg]   (recompute, same bits)
// ---------------------------------------------------------------------------
__global__ void __launch_bounds__(256)
k_div(const int* __restrict__ nb, float* __restrict__ out, int n) {
    int i = blockIdx.x * blockDim.x + threadIdx.x;
    if (i < n) {
        int   seg = nb[i];
        float mx  = dec_f(g_maxenc[seg]);
        float e   = __expf(g_logit[i] - mx);
        out[i] = e / g_sum[seg];
    }
}

// ---------------------------------------------------------------------------
extern "C" void kernel_launch(void* const* d_in, const int* in_sizes, int n_in,
                              void* d_out, int out_size) {
    const float* x   = (const float*)d_in[0];
    const int*   nb  = (const int*)d_in[1];
    const float* gf  = (const float*)d_in[2];
    const float* W1  = (const float*)d_in[3];
    const float* b1  = (const float*)d_in[4];
    const float* W2  = (const float*)d_in[5];
    const float* b2  = (const float*)d_in[6];
    float*       out = (float*)d_out;

    int n = in_sizes[0] / NEU;   // nodes
    int b = in_sizes[2] / GD;    // graphs

    k_init<<<(b + 255) / 256, 256>>>(b);
    k_graph<<<(b + 7) / 8, 256>>>(gf, W1, b1, b);

    int blocks = (n + 255) / 256;
    k_logits<<<blocks, 256>>>(x, nb, W1, W2, b2, n);
    k_exp<<<blocks, 256>>>(nb, n);
    k_div<<<blocks, 256>>>(nb, out, n);
}